// round 17
// baseline (speedup 1.0000x reference)
#include <cuda_runtime.h>
#include <cuda_bf16.h>
#include <cstdint>

// Problem constants (fixed by the dataset)
#define NV 8192
#define DV 128
#define GT 64              // 128-row tiles per dim
#define NTJH 128           // 64-col half-tiles per dim
#define ACTIVE_CTAS 4160   // 2 * (64*65/2)
#define FXSCALE 67108864.0 // 2^26

// -------- device scratch (no allocs allowed) --------
__device__ __nv_bfloat16 g_wbf[(size_t)NV * DV];   // bf16 weights (2 MB, L2-resident)
__device__ float g_sq[NV];                          // fp32 row squared norms
__device__ unsigned long long g_acc;                // fixed-point global sum
__device__ unsigned int g_done;                     // completion ticket

// ============================================================
// Helpers (portable PTX only: compute_103 virtual target)
// ============================================================
static __device__ __forceinline__ uint32_t smem_u32(const void* p) {
    uint32_t a;
    asm("{ .reg .u64 t; cvta.to.shared.u64 t, %1; cvt.u32.u64 %0, t; }"
        : "=r"(a) : "l"(p));
    return a;
}
static __device__ __forceinline__ float fsqrt_fast(float x) {
    float r; asm("sqrt.approx.f32 %0, %1;" : "=f"(r) : "f"(x)); return r;
}
static __device__ __forceinline__ void ldsm_x4(uint32_t& r0, uint32_t& r1,
                                               uint32_t& r2, uint32_t& r3,
                                               uint32_t addr) {
    asm volatile("ldmatrix.sync.aligned.m8n8.x4.shared.b16 {%0,%1,%2,%3}, [%4];"
                 : "=r"(r0), "=r"(r1), "=r"(r2), "=r"(r3) : "r"(addr));
}
static __device__ __forceinline__ void ldsm_x2(uint32_t& r0, uint32_t& r1,
                                               uint32_t addr) {
    asm volatile("ldmatrix.sync.aligned.m8n8.x2.shared.b16 {%0,%1}, [%2];"
                 : "=r"(r0), "=r"(r1) : "r"(addr));
}
static __device__ __forceinline__ void mma16816(float* d, const uint32_t* a,
                                                const uint32_t* b) {
    asm volatile(
        "mma.sync.aligned.m16n8k16.row.col.f32.bf16.bf16.f32 "
        "{%0,%1,%2,%3}, {%4,%5,%6,%7}, {%8,%9}, {%0,%1,%2,%3};"
        : "+f"(d[0]), "+f"(d[1]), "+f"(d[2]), "+f"(d[3])
        : "r"(a[0]), "r"(a[1]), "r"(a[2]), "r"(a[3]), "r"(b[0]), "r"(b[1]));
}

// W K=32 slice tile: rows x 32 bf16 = 64 B/row.
// Row r, 16B chunk c in 0..3; physical chunk = c ^ ((r>>1)&3).
static __device__ __forceinline__ uint32_t w_off32(int row, int c) {
    return (uint32_t)(row * 64 + ((c ^ ((row >> 1) & 3)) << 4));
}

// ============================================================
// Kernel 1: fp32 weights -> bf16 buffer + squared norms
// ============================================================
__global__ void prep_kernel(const float* __restrict__ w) {
    int t = blockIdx.x * blockDim.x + threadIdx.x;
    int row = t >> 5;
    int lid = t & 31;
    if (row >= NV) return;
    float4 v = reinterpret_cast<const float4*>(w + (size_t)row * DV)[lid];
    __nv_bfloat162 p0 = __float22bfloat162_rn(make_float2(v.x, v.y));
    __nv_bfloat162 p1 = __float22bfloat162_rn(make_float2(v.z, v.w));
    uint2 pk;
    pk.x = *reinterpret_cast<uint32_t*>(&p0);
    pk.y = *reinterpret_cast<uint32_t*>(&p1);
    *reinterpret_cast<uint2*>(&g_wbf[(size_t)row * DV + lid * 4]) = pk;
    float s = v.x * v.x + v.y * v.y + v.z * v.z + v.w * v.w;
    #pragma unroll
    for (int o = 16; o; o >>= 1) s += __shfl_xor_sync(0xffffffffu, s, o);
    if (lid == 0) g_sq[row] = s;
}

// ============================================================
// Kernel 2: 128x64 half-tiles, symmetric (tile-col-half's parent >= tile-row).
// 8 warps 2(m) x 4(n); warp tile 64x16; K=128 in four K=32 SMEM slices.
// 3 CTAs/SM target. Deterministic fixed-point atomic accumulation; last CTA
// writes the final scalar.
// ============================================================
__global__ __launch_bounds__(256, 3)
void tile_kernel(const float* __restrict__ A, float* __restrict__ out) {
    const int tjh = blockIdx.x;          // 0..127 (64-col half-tile)
    const int ti  = blockIdx.y;          // 0..63  (128-row tile)
    const int tj  = tjh >> 1;
    if (tj < ti) return;                 // symmetry: lower triangle folded in
    const bool diag = (tj == ti);

    __shared__ __align__(16) char s_wm[128 * 64];   // 8 KB (128 rows, K=32 slice)
    __shared__ __align__(16) char s_wn[64 * 64];    // 4 KB (64 rows,  K=32 slice)
    __shared__ float sred[8];

    const uint32_t sbm = smem_u32(s_wm);
    const uint32_t sbn = smem_u32(s_wn);
    const int tid = threadIdx.x;
    const int wid = tid >> 5;
    const int lid = tid & 31;
    const int wm = wid >> 2;             // 0..1 (m block of 64)
    const int wn = wid & 3;              // 0..3 (n block of 16)
    const int m0 = ti * 128;
    const int n0 = tjh * 64;
    const int q  = lid >> 2;             // 0..7
    const int t4 = lid & 3;

    // --- A prefetch for mi=0 (in registers, flows during the MMA mainloop) ---
    float2 cd0[2], cd8[2];
    float  ct[2][4];
    {
        const int R = wm * 64 + q;       // mi = 0
        #pragma unroll
        for (int ni = 0; ni < 2; ni++) {
            const int c0 = n0 + wn * 16 + ni * 8 + 2 * t4;
            cd0[ni] = __ldg(reinterpret_cast<const float2*>(
                A + (size_t)(m0 + R) * NV + c0));
            cd8[ni] = __ldg(reinterpret_cast<const float2*>(
                A + (size_t)(m0 + R + 8) * NV + c0));
            if (!diag) {
                const float* At = A + (size_t)c0 * NV + (m0 + R);
                ct[ni][0] = __ldg(At);
                ct[ni][1] = __ldg(At + NV);
                ct[ni][2] = __ldg(At + 8);
                ct[ni][3] = __ldg(At + NV + 8);
            } else {
                ct[ni][0] = ct[ni][1] = ct[ni][2] = ct[ni][3] = 0.0f;
            }
        }
    }
    // column squared norms for this thread's n positions
    float sn0r[2], sn1r[2];
    #pragma unroll
    for (int ni = 0; ni < 2; ni++) {
        int c0 = n0 + wn * 16 + ni * 8 + 2 * t4;
        sn0r[ni] = __ldg(&g_sq[c0]);
        sn1r[ni] = __ldg(&g_sq[c0 + 1]);
    }

    float acc[4][2][4];
    #pragma unroll
    for (int mi = 0; mi < 4; mi++)
        #pragma unroll
        for (int ni = 0; ni < 2; ni++)
            #pragma unroll
            for (int e = 0; e < 4; e++) acc[mi][ni][e] = 0.0f;

    // --- mainloop: four K=32 slices ---
    #pragma unroll
    for (int kt = 0; kt < 4; kt++) {
        // stage Wm (512 chunks) + Wn (256 chunks)
        #pragma unroll
        for (int it = 0; it < 2; it++) {
            int i = tid + it * 256;          // 0..511
            int row = i >> 2, c = i & 3;
            const size_t gk = (size_t)kt * 32 + c * 8;
            uint4 vm = *reinterpret_cast<const uint4*>(
                &g_wbf[(size_t)(m0 + row) * DV + gk]);
            *reinterpret_cast<uint4*>(s_wm + w_off32(row, c)) = vm;
        }
        {
            int row = tid >> 2, c = tid & 3;
            const size_t gk = (size_t)kt * 32 + c * 8;
            uint4 vn = *reinterpret_cast<const uint4*>(
                &g_wbf[(size_t)(n0 + row) * DV + gk]);
            *reinterpret_cast<uint4*>(s_wn + w_off32(row, c)) = vn;
        }
        __syncthreads();

        #pragma unroll
        for (int ks = 0; ks < 2; ks++) {
            uint32_t bf[2][2];
            #pragma unroll
            for (int ni = 0; ni < 2; ni++) {
                int row = wn * 16 + ni * 8 + (lid & 7);
                int ch  = ks * 2 + ((lid >> 3) & 1);
                ldsm_x2(bf[ni][0], bf[ni][1], sbn + w_off32(row, ch));
            }
            #pragma unroll
            for (int mi = 0; mi < 4; mi++) {
                uint32_t af[4];
                int row = wm * 64 + mi * 16 + (lid & 15);
                int ch  = ks * 2 + (lid >> 4);
                ldsm_x4(af[0], af[1], af[2], af[3], sbm + w_off32(row, ch));
                mma16816(acc[mi][0], af, bf[0]);
                mma16816(acc[mi][1], af, bf[1]);
            }
        }
        if (kt < 3) __syncthreads();
    }

    // --- epilogue: software-pipelined over mi ---
    float asum0 = 0.0f, asum1 = 0.0f;
    #pragma unroll
    for (int mi = 0; mi < 4; mi++) {
        float2 nd0[2], nd8[2];
        float  nt[2][4];
        if (mi < 3) {
            const int R = wm * 64 + (mi + 1) * 16 + q;
            #pragma unroll
            for (int ni = 0; ni < 2; ni++) {
                const int c0 = n0 + wn * 16 + ni * 8 + 2 * t4;
                nd0[ni] = __ldg(reinterpret_cast<const float2*>(
                    A + (size_t)(m0 + R) * NV + c0));
                nd8[ni] = __ldg(reinterpret_cast<const float2*>(
                    A + (size_t)(m0 + R + 8) * NV + c0));
                if (!diag) {
                    const float* At = A + (size_t)c0 * NV + (m0 + R);
                    nt[ni][0] = __ldg(At);
                    nt[ni][1] = __ldg(At + NV);
                    nt[ni][2] = __ldg(At + 8);
                    nt[ni][3] = __ldg(At + NV + 8);
                } else {
                    nt[ni][0] = nt[ni][1] = nt[ni][2] = nt[ni][3] = 0.0f;
                }
            }
        }
        const int R = wm * 64 + mi * 16 + q;
        const float sqm0 = __ldg(&g_sq[m0 + R]);
        const float sqm8 = __ldg(&g_sq[m0 + R + 8]);
        #pragma unroll
        for (int ni = 0; ni < 2; ni++) {
            float d0 = fmaxf(sqm0 + sn0r[ni] - 2.0f * acc[mi][ni][0], 0.0f);
            float d1 = fmaxf(sqm0 + sn1r[ni] - 2.0f * acc[mi][ni][1], 0.0f);
            float d2 = fmaxf(sqm8 + sn0r[ni] - 2.0f * acc[mi][ni][2], 0.0f);
            float d3 = fmaxf(sqm8 + sn1r[ni] - 2.0f * acc[mi][ni][3], 0.0f);
            asum0 = fmaf(cd0[ni].x + ct[ni][0], fsqrt_fast(d0), asum0);
            asum1 = fmaf(cd0[ni].y + ct[ni][1], fsqrt_fast(d1), asum1);
            asum0 = fmaf(cd8[ni].x + ct[ni][2], fsqrt_fast(d2), asum0);
            asum1 = fmaf(cd8[ni].y + ct[ni][3], fsqrt_fast(d3), asum1);
        }
        if (mi < 3) {
            #pragma unroll
            for (int ni = 0; ni < 2; ni++) {
                cd0[ni] = nd0[ni]; cd8[ni] = nd8[ni];
                #pragma unroll
                for (int e = 0; e < 4; e++) ct[ni][e] = nt[ni][e];
            }
        }
    }
    float asum = asum0 + asum1;

    // --- deterministic reduction: warp -> smem -> thread 0 -> fixed point ---
    #pragma unroll
    for (int o = 16; o; o >>= 1) asum += __shfl_xor_sync(0xffffffffu, asum, o);
    if (lid == 0) sred[wid] = asum;
    __syncthreads();
    if (tid == 0) {
        float s = ((sred[0] + sred[1]) + (sred[2] + sred[3]))
                + ((sred[4] + sred[5]) + (sred[6] + sred[7]));
        unsigned long long qv =
            (unsigned long long)((double)s * FXSCALE + 0.5);
        atomicAdd(&g_acc, qv);
        __threadfence();
        unsigned int t = atomicAdd(&g_done, 1u);
        if (t == ACTIVE_CTAS - 1) {
            __threadfence();
            unsigned long long v = atomicAdd(&g_acc, 0ULL);
            out[0] = (float)((double)v * (1.0 / FXSCALE));
            atomicExch(&g_acc, 0ULL);     // reset for next graph replay
            atomicExch(&g_done, 0u);
        }
    }
}

// ============================================================
// kernel_launch — plain launches only, no attribute calls, no opt-ins
// ============================================================
extern "C" void kernel_launch(void* const* d_in, const int* in_sizes, int n_in,
                              void* d_out, int out_size) {
    const float* A = (const float*)d_in[0];       // [N, N]
    const float* W = (const float*)d_in[1];       // [N, D]
    float* out = (float*)d_out;                   // [1 + N*D]: result then weights

    // weights pass-through (exact copy), overlaps with compute
    if (out_size >= 1 + NV * DV) {
        cudaMemcpyAsync(out + 1, W, (size_t)NV * DV * sizeof(float),
                        cudaMemcpyDeviceToDevice, 0);
    }

    prep_kernel<<<(NV * 32) / 256, 256>>>(W);

    dim3 grid(NTJH, GT);
    tile_kernel<<<grid, 256>>>(A, out);
}